// round 1
// baseline (speedup 1.0000x reference)
#include <cuda_runtime.h>
#include <math.h>

#define BB 4
#define NN 50000
#define KK 128
#define GD 128
#define TPB 256
#define NBLK ((NN + TPB - 1) / TPB)   // 196
#define TOTAL_BLK (BB * NBLK)          // 784

// Per-(b,k) packed params: 5 float4 each
//  p0 = (R00,R01,R02, cx)
//  p1 = (R10,R11,R12, cy)
//  p2 = (R20,R21,R22, cz)
//  p3 = (ct0,ct1,ct2, a)   a = -log2(e)/(2 s^2)
//  p4 = (lb, 0,0,0)        lb = log2(c^2)
__device__ float4 g_params[BB * KK * 5];
__device__ float  g_partial[TOTAL_BLK];

__global__ void precompute_kernel(const float* __restrict__ constants,
                                  const float* __restrict__ scales,
                                  const float* __restrict__ rot,
                                  const float* __restrict__ centers) {
    int idx = blockIdx.x * blockDim.x + threadIdx.x;
    if (idx >= BB * KK) return;
    int b = idx / KK;
    int k = idx - b * KK;
    int bt = (b + 1) & 3;

    const float* R  = rot + ((size_t)(b  * KK + k)) * 9;
    const float* Rt = rot + ((size_t)(bt * KK + k)) * 9;

    float Rrel[3][3];
#pragma unroll
    for (int i = 0; i < 3; i++)
#pragma unroll
        for (int l = 0; l < 3; l++)
            Rrel[i][l] = Rt[i*3+0]*R[l*3+0] + Rt[i*3+1]*R[l*3+1] + Rt[i*3+2]*R[l*3+2];

    const float* c  = centers + ((size_t)(b  * KK + k)) * 3;
    const float* ct = centers + ((size_t)(bt * KK + k)) * 3;
    float s  = scales[b * KK + k];
    float cc = constants[b * KK + k];
    const float LOG2E = 1.4426950408889634f;
    float a  = -LOG2E / (2.0f * s * s);
    float lb = log2f(cc * cc);

    float4* p = g_params + idx * 5;
    p[0] = make_float4(Rrel[0][0], Rrel[0][1], Rrel[0][2], c[0]);
    p[1] = make_float4(Rrel[1][0], Rrel[1][1], Rrel[1][2], c[1]);
    p[2] = make_float4(Rrel[2][0], Rrel[2][1], Rrel[2][2], c[2]);
    p[3] = make_float4(ct[0], ct[1], ct[2], a);
    p[4] = make_float4(lb, 0.f, 0.f, 0.f);
}

__global__ __launch_bounds__(TPB)
void main_kernel(const float* __restrict__ samples,
                 const float* __restrict__ grid,
                 const float* __restrict__ w2g) {
    int b   = blockIdx.x / NBLK;
    int blk = blockIdx.x - b * NBLK;
    int n   = blk * TPB + threadIdx.x;

    __shared__ float4 sp[KK * 5];
    {
        const float4* src = g_params + (size_t)b * KK * 5;
        for (int i = threadIdx.x; i < KK * 5; i += TPB) sp[i] = src[i];
    }
    __syncthreads();

    float val = 0.0f;
    if (n < NN) {
        const float* s6 = samples + ((size_t)b * NN + n) * 6;
        float px = s6[0], py = s6[1], pz = s6[2];

        float wsum = 0.f, ax = 0.f, ay = 0.f, az = 0.f;
#pragma unroll 4
        for (int k = 0; k < KK; k++) {
            float4 f0 = sp[k*5 + 0];
            float4 f1 = sp[k*5 + 1];
            float4 f2 = sp[k*5 + 2];
            float4 f3 = sp[k*5 + 3];
            float4 f4 = sp[k*5 + 4];
            float dx = px - f0.w;
            float dy = py - f1.w;
            float dz = pz - f2.w;
            float d2 = fmaf(dx, dx, fmaf(dy, dy, dz * dz));
            float w  = exp2f(fmaf(d2, f3.w, f4.x));
            float tx = fmaf(f0.x, dx, fmaf(f0.y, dy, fmaf(f0.z, dz, f3.x)));
            float ty = fmaf(f1.x, dx, fmaf(f1.y, dy, fmaf(f1.z, dz, f3.y)));
            float tz = fmaf(f2.x, dx, fmaf(f2.y, dy, fmaf(f2.z, dz, f3.z)));
            wsum += w;
            ax = fmaf(w, tx, ax);
            ay = fmaf(w, ty, ay);
            az = fmaf(w, tz, az);
        }
        float inv = 1.0f / wsum;
        float bx = ax * inv, by = ay * inv, bz = az * inv;

        int bt = (b + 1) & 3;
        const float* M = w2g + bt * 16;
        float gx = M[0]*bx + M[1]*by + M[2]*bz  + M[3];
        float gy = M[4]*bx + M[5]*by + M[6]*bz  + M[7];
        float gz = M[8]*bx + M[9]*by + M[10]*bz + M[11];

        // normalize to [-1,1] then back to grid coords (match reference arithmetic)
        const float dm = (float)(GD - 1);
        float nx = 2.0f * (gx / dm) - 1.0f;
        float ny = 2.0f * (gy / dm) - 1.0f;
        float nz = 2.0f * (gz / dm) - 1.0f;

        float x = fminf(fmaxf((nx + 1.0f) * 0.5f * dm, 0.0f), dm);
        float y = fminf(fmaxf((ny + 1.0f) * 0.5f * dm, 0.0f), dm);
        float z = fminf(fmaxf((nz + 1.0f) * 0.5f * dm, 0.0f), dm);

        float x0f = floorf(x), y0f = floorf(y), z0f = floorf(z);
        float fx = x - x0f, fy = y - y0f, fz = z - z0f;
        int x0 = (int)x0f, y0 = (int)y0f, z0 = (int)z0f;
        int x1 = min(x0 + 1, GD - 1);
        int y1 = min(y0 + 1, GD - 1);
        int z1 = min(z0 + 1, GD - 1);

        const float* g = grid + (size_t)bt * GD * GD * GD;
        int zy00 = (z0 * GD + y0) * GD;
        int zy01 = (z0 * GD + y1) * GD;
        int zy10 = (z1 * GD + y0) * GD;
        int zy11 = (z1 * GD + y1) * GD;
        float c000 = __ldg(g + zy00 + x0);
        float c001 = __ldg(g + zy00 + x1);
        float c010 = __ldg(g + zy01 + x0);
        float c011 = __ldg(g + zy01 + x1);
        float c100 = __ldg(g + zy10 + x0);
        float c101 = __ldg(g + zy10 + x1);
        float c110 = __ldg(g + zy11 + x0);
        float c111 = __ldg(g + zy11 + x1);

        float c00 = c000 + (c001 - c000) * fx;
        float c01 = c010 + (c011 - c010) * fx;
        float c10 = c100 + (c101 - c100) * fx;
        float c11 = c110 + (c111 - c110) * fx;
        float c0  = c00 + (c01 - c00) * fy;
        float c1  = c10 + (c11 - c10) * fy;
        float sdf = c0 + (c1 - c0) * fz;
        val = sdf * sdf;
    }

    // deterministic block reduction
    __shared__ float red[TPB];
    red[threadIdx.x] = val;
    __syncthreads();
#pragma unroll
    for (int s = TPB / 2; s > 0; s >>= 1) {
        if (threadIdx.x < s) red[threadIdx.x] += red[threadIdx.x + s];
        __syncthreads();
    }
    if (threadIdx.x == 0) g_partial[blockIdx.x] = red[0];
}

__global__ void finalize_kernel(float* __restrict__ out) {
    __shared__ float red[256];
    float s = 0.0f;
    for (int i = threadIdx.x; i < TOTAL_BLK; i += 256) s += g_partial[i];
    red[threadIdx.x] = s;
    __syncthreads();
#pragma unroll
    for (int st = 128; st > 0; st >>= 1) {
        if (threadIdx.x < st) red[threadIdx.x] += red[threadIdx.x + st];
        __syncthreads();
    }
    if (threadIdx.x == 0) out[0] = red[0] * (1.0f / (float)NN);
}

extern "C" void kernel_launch(void* const* d_in, const int* in_sizes, int n_in,
                              void* d_out, int out_size) {
    const float* constants = (const float*)d_in[0];   // (B,K)
    const float* scales    = (const float*)d_in[1];   // (B,K)
    const float* rotations = (const float*)d_in[2];   // (B,K,3,3)
    const float* centers   = (const float*)d_in[3];   // (B,K,3)
    const float* samples   = (const float*)d_in[4];   // (B,N,6)
    const float* grid      = (const float*)d_in[5];   // (B,GD,GD,GD)
    const float* w2g       = (const float*)d_in[6];   // (B,4,4)
    float* out = (float*)d_out;

    precompute_kernel<<<(BB * KK + 255) / 256, 256>>>(constants, scales, rotations, centers);
    main_kernel<<<TOTAL_BLK, TPB>>>(samples, grid, w2g);
    finalize_kernel<<<1, 256>>>(out);
}

// round 2
// speedup vs baseline: 1.1876x; 1.1876x over previous
#include <cuda_runtime.h>
#include <math.h>

#define BB 4
#define NN 50000
#define KK 128
#define NP (KK/2)                      // 64 packed pairs
#define GD 128
#define TPB 256
#define NBLK ((NN + TPB - 1) / TPB)    // 196
#define TOTAL_BLK (BB * NBLK)          // 784

__device__ float        g_partial[TOTAL_BLK];
__device__ unsigned int g_count = 0;

__device__ __forceinline__ float ex2f(float x) {
    float y; asm("ex2.approx.ftz.f32 %0, %1;" : "=f"(y) : "f"(x)); return y;
}

union F2U { float2 f; unsigned long long u; };

__device__ __forceinline__ float2 fma2(float2 a, float2 b, float2 c) {
    F2U A, B, C, D; A.f = a; B.f = b; C.f = c;
    asm("fma.rn.f32x2 %0, %1, %2, %3;" : "=l"(D.u) : "l"(A.u), "l"(B.u), "l"(C.u));
    return D.f;
}
__device__ __forceinline__ float2 add2(float2 a, float2 b) {
    F2U A, B, D; A.f = a; B.f = b;
    asm("add.rn.f32x2 %0, %1, %2;" : "=l"(D.u) : "l"(A.u), "l"(B.u));
    return D.f;
}
__device__ __forceinline__ float2 mul2(float2 a, float2 b) {
    F2U A, B, D; A.f = a; B.f = b;
    asm("mul.rn.f32x2 %0, %1, %2;" : "=l"(D.u) : "l"(A.u), "l"(B.u));
    return D.f;
}

// Pair-interleaved param layout in shared: for pair p (k=2p, 2p+1),
// 18 logical float2 values (lane 0 = even k, lane 1 = odd k), stored as
// 9 float4 (36 floats). Value index v:
//  0..2  = Rrel row0            3  = -cx
//  4..6  = Rrel row1            7  = -cy
//  8..10 = Rrel row2            11 = -cz
//  12..14 = ct                  15 = a  (= -log2e / 2s^2)
//  16 = lb (= log2(c^2))        17 = pad
__global__ __launch_bounds__(TPB, 3)
void fused_kernel(const float* __restrict__ constants,
                  const float* __restrict__ scales,
                  const float* __restrict__ rot,
                  const float* __restrict__ centers,
                  const float* __restrict__ samples,
                  const float* __restrict__ grid,
                  const float* __restrict__ w2g,
                  float* __restrict__ out) {
    int b   = blockIdx.x / NBLK;
    int blk = blockIdx.x - b * NBLK;
    int n   = blk * TPB + threadIdx.x;
    int bt  = (b + 1) & 3;

    __shared__ float spf[NP * 36];
    __shared__ float red[TPB];
    __shared__ bool  s_last;

    // ---- in-block precompute of per-(b,k) params (threads 0..127) ----
    {
        int k = threadIdx.x;
        if (k < KK) {
            const float* R  = rot + (size_t)(b  * KK + k) * 9;
            const float* Rt = rot + (size_t)(bt * KK + k) * 9;
            float v[18];
#pragma unroll
            for (int i = 0; i < 3; i++)
#pragma unroll
                for (int l = 0; l < 3; l++)
                    v[i * 4 + l] = Rt[i*3+0]*R[l*3+0] + Rt[i*3+1]*R[l*3+1] + Rt[i*3+2]*R[l*3+2];
            const float* c  = centers + (size_t)(b  * KK + k) * 3;
            const float* ct = centers + (size_t)(bt * KK + k) * 3;
            v[3]  = -c[0];  v[7]  = -c[1];  v[11] = -c[2];
            v[12] = ct[0];  v[13] = ct[1];  v[14] = ct[2];
            float s  = scales[b * KK + k];
            float cc = constants[b * KK + k];
            v[15] = -1.4426950408889634f / (2.0f * s * s);
            v[16] = log2f(cc * cc);
            v[17] = 0.0f;
            int p = k >> 1, lane = k & 1;
            float* dst = spf + p * 36 + lane;
#pragma unroll
            for (int vi = 0; vi < 18; vi++) dst[2 * vi] = v[vi];
        }
    }
    __syncthreads();

    float val = 0.0f;
    if (n < NN) {
        const float* s6 = samples + (size_t)(b * NN + n) * 6;
        float px = s6[0], py = s6[1], pz = s6[2];
        float2 px2 = make_float2(px, px);
        float2 py2 = make_float2(py, py);
        float2 pz2 = make_float2(pz, pz);
        float2 wsum = make_float2(0.f, 0.f);
        float2 axx  = make_float2(0.f, 0.f);
        float2 ayy  = make_float2(0.f, 0.f);
        float2 azz  = make_float2(0.f, 0.f);

        const float4* sp4 = (const float4*)spf;
#pragma unroll 2
        for (int p = 0; p < NP; p++) {
            float4 f0 = sp4[p*9+0], f1 = sp4[p*9+1], f2 = sp4[p*9+2];
            float4 f3 = sp4[p*9+3], f4 = sp4[p*9+4], f5 = sp4[p*9+5];
            float4 f6 = sp4[p*9+6], f7 = sp4[p*9+7], f8 = sp4[p*9+8];
            float2 q0  = make_float2(f0.x, f0.y), q1  = make_float2(f0.z, f0.w);
            float2 q2  = make_float2(f1.x, f1.y), q3  = make_float2(f1.z, f1.w);
            float2 q4  = make_float2(f2.x, f2.y), q5  = make_float2(f2.z, f2.w);
            float2 q6  = make_float2(f3.x, f3.y), q7  = make_float2(f3.z, f3.w);
            float2 q8  = make_float2(f4.x, f4.y), q9  = make_float2(f4.z, f4.w);
            float2 q10 = make_float2(f5.x, f5.y), q11 = make_float2(f5.z, f5.w);
            float2 q12 = make_float2(f6.x, f6.y), q13 = make_float2(f6.z, f6.w);
            float2 q14 = make_float2(f7.x, f7.y), q15 = make_float2(f7.z, f7.w);
            float2 q16 = make_float2(f8.x, f8.y);

            float2 dx = add2(px2, q3);
            float2 dy = add2(py2, q7);
            float2 dz = add2(pz2, q11);
            float2 d2 = fma2(dz, dz, fma2(dy, dy, mul2(dx, dx)));
            float2 arg = fma2(d2, q15, q16);
            float2 w;
            w.x = ex2f(arg.x);
            w.y = ex2f(arg.y);
            float2 tx = fma2(q0, dx, fma2(q1, dy, fma2(q2,  dz, q12)));
            float2 ty = fma2(q4, dx, fma2(q5, dy, fma2(q6,  dz, q13)));
            float2 tz = fma2(q8, dx, fma2(q9, dy, fma2(q10, dz, q14)));
            wsum = add2(wsum, w);
            axx = fma2(w, tx, axx);
            ayy = fma2(w, ty, ayy);
            azz = fma2(w, tz, azz);
        }

        float ws  = wsum.x + wsum.y;
        float inv = 1.0f / ws;
        float bx = (axx.x + axx.y) * inv;
        float by = (ayy.x + ayy.y) * inv;
        float bz = (azz.x + azz.y) * inv;

        const float* M = w2g + bt * 16;
        float gx = M[0]*bx + M[1]*by + M[2]*bz  + M[3];
        float gy = M[4]*bx + M[5]*by + M[6]*bz  + M[7];
        float gz = M[8]*bx + M[9]*by + M[10]*bz + M[11];

        const float dm = (float)(GD - 1);
        float nx = 2.0f * (gx / dm) - 1.0f;
        float ny = 2.0f * (gy / dm) - 1.0f;
        float nz = 2.0f * (gz / dm) - 1.0f;

        float x = fminf(fmaxf((nx + 1.0f) * 0.5f * dm, 0.0f), dm);
        float y = fminf(fmaxf((ny + 1.0f) * 0.5f * dm, 0.0f), dm);
        float z = fminf(fmaxf((nz + 1.0f) * 0.5f * dm, 0.0f), dm);

        float x0f = floorf(x), y0f = floorf(y), z0f = floorf(z);
        float fx = x - x0f, fy = y - y0f, fz = z - z0f;
        int x0 = (int)x0f, y0 = (int)y0f, z0 = (int)z0f;
        int x1 = min(x0 + 1, GD - 1);
        int y1 = min(y0 + 1, GD - 1);
        int z1 = min(z0 + 1, GD - 1);

        const float* g = grid + (size_t)bt * GD * GD * GD;
        int zy00 = (z0 * GD + y0) * GD;
        int zy01 = (z0 * GD + y1) * GD;
        int zy10 = (z1 * GD + y0) * GD;
        int zy11 = (z1 * GD + y1) * GD;
        float c000 = __ldg(g + zy00 + x0);
        float c001 = __ldg(g + zy00 + x1);
        float c010 = __ldg(g + zy01 + x0);
        float c011 = __ldg(g + zy01 + x1);
        float c100 = __ldg(g + zy10 + x0);
        float c101 = __ldg(g + zy10 + x1);
        float c110 = __ldg(g + zy11 + x0);
        float c111 = __ldg(g + zy11 + x1);

        float c00 = c000 + (c001 - c000) * fx;
        float c01 = c010 + (c011 - c010) * fx;
        float c10 = c100 + (c101 - c100) * fx;
        float c11 = c110 + (c111 - c110) * fx;
        float c0  = c00 + (c01 - c00) * fy;
        float c1  = c10 + (c11 - c10) * fy;
        float sdf = c0 + (c1 - c0) * fz;
        val = sdf * sdf;
    }

    // ---- deterministic block reduction ----
    red[threadIdx.x] = val;
    __syncthreads();
#pragma unroll
    for (int s = TPB / 2; s > 0; s >>= 1) {
        if (threadIdx.x < s) red[threadIdx.x] += red[threadIdx.x + s];
        __syncthreads();
    }
    if (threadIdx.x == 0) {
        g_partial[blockIdx.x] = red[0];
        __threadfence();
        unsigned int t = atomicAdd(&g_count, 1u);
        s_last = (t == TOTAL_BLK - 1);
    }
    __syncthreads();

    // ---- last block finalizes (fixed-order, deterministic) ----
    if (s_last) {
        float s = 0.0f;
        for (int i = threadIdx.x; i < TOTAL_BLK; i += TPB) s += g_partial[i];
        red[threadIdx.x] = s;
        __syncthreads();
#pragma unroll
        for (int st = TPB / 2; st > 0; st >>= 1) {
            if (threadIdx.x < st) red[threadIdx.x] += red[threadIdx.x + st];
            __syncthreads();
        }
        if (threadIdx.x == 0) {
            out[0] = red[0] * (1.0f / (float)NN);
            g_count = 0;   // reset for next graph replay
        }
    }
}

extern "C" void kernel_launch(void* const* d_in, const int* in_sizes, int n_in,
                              void* d_out, int out_size) {
    const float* constants = (const float*)d_in[0];   // (B,K)
    const float* scales    = (const float*)d_in[1];   // (B,K)
    const float* rotations = (const float*)d_in[2];   // (B,K,3,3)
    const float* centers   = (const float*)d_in[3];   // (B,K,3)
    const float* samples   = (const float*)d_in[4];   // (B,N,6)
    const float* grid      = (const float*)d_in[5];   // (B,GD,GD,GD)
    const float* w2g       = (const float*)d_in[6];   // (B,4,4)
    float* out = (float*)d_out;

    fused_kernel<<<TOTAL_BLK, TPB>>>(constants, scales, rotations, centers,
                                     samples, grid, w2g, out);
}

// round 3
// speedup vs baseline: 1.5113x; 1.2725x over previous
#include <cuda_runtime.h>
#include <math.h>

#define BB 4
#define NN 50000
#define KK 128
#define NP (KK/2)                      // 64 packed gaussian pairs
#define GD 128
#define TPB 256
#define PPT 2                          // points per thread
#define PPB (TPB * PPT)                // 512 points per block
#define NBLK ((NN + PPB - 1) / PPB)    // 98
#define TOTAL_BLK (BB * NBLK)          // 392

__device__ float        g_partial[TOTAL_BLK];
__device__ unsigned int g_count = 0;

__device__ __forceinline__ float ex2f(float x) {
    float y; asm("ex2.approx.ftz.f32 %0, %1;" : "=f"(y) : "f"(x)); return y;
}

union F2U { float2 f; unsigned long long u; };

__device__ __forceinline__ float2 fma2(float2 a, float2 b, float2 c) {
    F2U A, B, C, D; A.f = a; B.f = b; C.f = c;
    asm("fma.rn.f32x2 %0, %1, %2, %3;" : "=l"(D.u) : "l"(A.u), "l"(B.u), "l"(C.u));
    return D.f;
}
__device__ __forceinline__ float2 add2(float2 a, float2 b) {
    F2U A, B, D; A.f = a; B.f = b;
    asm("add.rn.f32x2 %0, %1, %2;" : "=l"(D.u) : "l"(A.u), "l"(B.u));
    return D.f;
}
__device__ __forceinline__ float2 mul2(float2 a, float2 b) {
    F2U A, B, D; A.f = a; B.f = b;
    asm("mul.rn.f32x2 %0, %1, %2;" : "=l"(D.u) : "l"(A.u), "l"(B.u));
    return D.f;
}

// Pair-interleaved param layout (per gaussian pair p, lanes = even/odd k):
//  v0..2 = Rrel row0   v3  = -cx
//  v4..6 = Rrel row1   v7  = -cy
//  v8..10= Rrel row2   v11 = -cz
//  v12..14 = ct        v15 = a  (= -log2e / 2s^2)
//  v16 = lb (= log2(c^2))   v17 = pad
__global__ __launch_bounds__(TPB, 2)
void fused_kernel(const float* __restrict__ constants,
                  const float* __restrict__ scales,
                  const float* __restrict__ rot,
                  const float* __restrict__ centers,
                  const float* __restrict__ samples,
                  const float* __restrict__ grid,
                  const float* __restrict__ w2g,
                  float* __restrict__ out) {
    int b   = blockIdx.x / NBLK;
    int blk = blockIdx.x - b * NBLK;
    int bt  = (b + 1) & 3;
    int n0  = blk * PPB + threadIdx.x;          // point A
    int n1  = n0 + TPB;                          // point B

    __shared__ float spf[NP * 36];
    __shared__ float red[TPB];
    __shared__ bool  s_last;

    // ---- in-block precompute of per-(b,k) params ----
    {
        int k = threadIdx.x;
        if (k < KK) {
            const float* R  = rot + (size_t)(b  * KK + k) * 9;
            const float* Rt = rot + (size_t)(bt * KK + k) * 9;
            float v[18];
#pragma unroll
            for (int i = 0; i < 3; i++)
#pragma unroll
                for (int l = 0; l < 3; l++)
                    v[i * 4 + l] = Rt[i*3+0]*R[l*3+0] + Rt[i*3+1]*R[l*3+1] + Rt[i*3+2]*R[l*3+2];
            const float* c  = centers + (size_t)(b  * KK + k) * 3;
            const float* ct = centers + (size_t)(bt * KK + k) * 3;
            v[3]  = -c[0];  v[7]  = -c[1];  v[11] = -c[2];
            v[12] = ct[0];  v[13] = ct[1];  v[14] = ct[2];
            float s  = scales[b * KK + k];
            float cc = constants[b * KK + k];
            v[15] = -1.4426950408889634f / (2.0f * s * s);
            v[16] = log2f(cc * cc);
            v[17] = 0.0f;
            int p = k >> 1, lane = k & 1;
            float* dst = spf + p * 36 + lane;
#pragma unroll
            for (int vi = 0; vi < 18; vi++) dst[2 * vi] = v[vi];
        }
    }
    __syncthreads();

    bool okA = (n0 < NN);
    bool okB = (n1 < NN);

    float pxA = 0.f, pyA = 0.f, pzA = 0.f;
    float pxB = 0.f, pyB = 0.f, pzB = 0.f;
    if (okA) {
        const float* s6 = samples + (size_t)(b * NN + n0) * 6;
        pxA = s6[0]; pyA = s6[1]; pzA = s6[2];
    }
    if (okB) {
        const float* s6 = samples + (size_t)(b * NN + n1) * 6;
        pxB = s6[0]; pyB = s6[1]; pzB = s6[2];
    }

    float2 pxA2 = make_float2(pxA, pxA), pyA2 = make_float2(pyA, pyA), pzA2 = make_float2(pzA, pzA);
    float2 pxB2 = make_float2(pxB, pxB), pyB2 = make_float2(pyB, pyB), pzB2 = make_float2(pzB, pzB);

    float2 wsA = make_float2(0.f,0.f), axA = wsA, ayA = wsA, azA = wsA;
    float2 wsB = make_float2(0.f,0.f), axB = wsB, ayB = wsB, azB = wsB;

    const float4* sp4 = (const float4*)spf;
#pragma unroll 2
    for (int p = 0; p < NP; p++) {
        float4 f0 = sp4[p*9+0], f1 = sp4[p*9+1], f2 = sp4[p*9+2];
        float4 f3 = sp4[p*9+3], f4 = sp4[p*9+4], f5 = sp4[p*9+5];
        float4 f6 = sp4[p*9+6], f7 = sp4[p*9+7], f8 = sp4[p*9+8];
        float2 q0  = make_float2(f0.x, f0.y), q1  = make_float2(f0.z, f0.w);
        float2 q2  = make_float2(f1.x, f1.y), q3  = make_float2(f1.z, f1.w);
        float2 q4  = make_float2(f2.x, f2.y), q5  = make_float2(f2.z, f2.w);
        float2 q6  = make_float2(f3.x, f3.y), q7  = make_float2(f3.z, f3.w);
        float2 q8  = make_float2(f4.x, f4.y), q9  = make_float2(f4.z, f4.w);
        float2 q10 = make_float2(f5.x, f5.y), q11 = make_float2(f5.z, f5.w);
        float2 q12 = make_float2(f6.x, f6.y), q13 = make_float2(f6.z, f6.w);
        float2 q14 = make_float2(f7.x, f7.y), q15 = make_float2(f7.z, f7.w);
        float2 q16 = make_float2(f8.x, f8.y);

        // ---- point A ----
        {
            float2 dx = add2(pxA2, q3);
            float2 dy = add2(pyA2, q7);
            float2 dz = add2(pzA2, q11);
            float2 d2 = fma2(dz, dz, fma2(dy, dy, mul2(dx, dx)));
            float2 arg = fma2(d2, q15, q16);
            float2 w;
            w.x = ex2f(arg.x);
            w.y = ex2f(arg.y);
            float2 tx = fma2(q0, dx, fma2(q1, dy, fma2(q2,  dz, q12)));
            float2 ty = fma2(q4, dx, fma2(q5, dy, fma2(q6,  dz, q13)));
            float2 tz = fma2(q8, dx, fma2(q9, dy, fma2(q10, dz, q14)));
            wsA = add2(wsA, w);
            axA = fma2(w, tx, axA);
            ayA = fma2(w, ty, ayA);
            azA = fma2(w, tz, azA);
        }
        // ---- point B ----
        {
            float2 dx = add2(pxB2, q3);
            float2 dy = add2(pyB2, q7);
            float2 dz = add2(pzB2, q11);
            float2 d2 = fma2(dz, dz, fma2(dy, dy, mul2(dx, dx)));
            float2 arg = fma2(d2, q15, q16);
            float2 w;
            w.x = ex2f(arg.x);
            w.y = ex2f(arg.y);
            float2 tx = fma2(q0, dx, fma2(q1, dy, fma2(q2,  dz, q12)));
            float2 ty = fma2(q4, dx, fma2(q5, dy, fma2(q6,  dz, q13)));
            float2 tz = fma2(q8, dx, fma2(q9, dy, fma2(q10, dz, q14)));
            wsB = add2(wsB, w);
            axB = fma2(w, tx, axB);
            ayB = fma2(w, ty, ayB);
            azB = fma2(w, tz, azB);
        }
    }

    const float* M = w2g + bt * 16;
    const float* g = grid + (size_t)bt * GD * GD * GD;
    const float dm = (float)(GD - 1);

    float val = 0.0f;
#pragma unroll
    for (int pt = 0; pt < 2; pt++) {
        bool ok = pt == 0 ? okA : okB;
        if (!ok) continue;
        float2 wsum = pt == 0 ? wsA : wsB;
        float2 axx  = pt == 0 ? axA : axB;
        float2 ayy  = pt == 0 ? ayA : ayB;
        float2 azz  = pt == 0 ? azA : azB;

        float ws  = wsum.x + wsum.y;
        float inv = 1.0f / ws;
        float bx = (axx.x + axx.y) * inv;
        float by = (ayy.x + ayy.y) * inv;
        float bz = (azz.x + azz.y) * inv;

        float gx = M[0]*bx + M[1]*by + M[2]*bz  + M[3];
        float gy = M[4]*bx + M[5]*by + M[6]*bz  + M[7];
        float gz = M[8]*bx + M[9]*by + M[10]*bz + M[11];

        float nx = 2.0f * (gx / dm) - 1.0f;
        float ny = 2.0f * (gy / dm) - 1.0f;
        float nz = 2.0f * (gz / dm) - 1.0f;

        float x = fminf(fmaxf((nx + 1.0f) * 0.5f * dm, 0.0f), dm);
        float y = fminf(fmaxf((ny + 1.0f) * 0.5f * dm, 0.0f), dm);
        float z = fminf(fmaxf((nz + 1.0f) * 0.5f * dm, 0.0f), dm);

        float x0f = floorf(x), y0f = floorf(y), z0f = floorf(z);
        float fx = x - x0f, fy = y - y0f, fz = z - z0f;
        int x0 = (int)x0f, y0 = (int)y0f, z0 = (int)z0f;
        int x1 = min(x0 + 1, GD - 1);
        int y1 = min(y0 + 1, GD - 1);
        int z1 = min(z0 + 1, GD - 1);

        int zy00 = (z0 * GD + y0) * GD;
        int zy01 = (z0 * GD + y1) * GD;
        int zy10 = (z1 * GD + y0) * GD;
        int zy11 = (z1 * GD + y1) * GD;
        float c000 = __ldg(g + zy00 + x0);
        float c001 = __ldg(g + zy00 + x1);
        float c010 = __ldg(g + zy01 + x0);
        float c011 = __ldg(g + zy01 + x1);
        float c100 = __ldg(g + zy10 + x0);
        float c101 = __ldg(g + zy10 + x1);
        float c110 = __ldg(g + zy11 + x0);
        float c111 = __ldg(g + zy11 + x1);

        float c00 = c000 + (c001 - c000) * fx;
        float c01 = c010 + (c011 - c010) * fx;
        float c10 = c100 + (c101 - c100) * fx;
        float c11 = c110 + (c111 - c110) * fx;
        float c0  = c00 + (c01 - c00) * fy;
        float c1  = c10 + (c11 - c10) * fy;
        float sdf = c0 + (c1 - c0) * fz;
        val += sdf * sdf;
    }

    // ---- deterministic block reduction ----
    red[threadIdx.x] = val;
    __syncthreads();
#pragma unroll
    for (int s = TPB / 2; s > 0; s >>= 1) {
        if (threadIdx.x < s) red[threadIdx.x] += red[threadIdx.x + s];
        __syncthreads();
    }
    if (threadIdx.x == 0) {
        g_partial[blockIdx.x] = red[0];
        __threadfence();
        unsigned int t = atomicAdd(&g_count, 1u);
        s_last = (t == TOTAL_BLK - 1);
    }
    __syncthreads();

    // ---- last block finalizes (fixed-order, deterministic) ----
    if (s_last) {
        float s = 0.0f;
        for (int i = threadIdx.x; i < TOTAL_BLK; i += TPB) s += g_partial[i];
        red[threadIdx.x] = s;
        __syncthreads();
#pragma unroll
        for (int st = TPB / 2; st > 0; st >>= 1) {
            if (threadIdx.x < st) red[threadIdx.x] += red[threadIdx.x + st];
            __syncthreads();
        }
        if (threadIdx.x == 0) {
            out[0] = red[0] * (1.0f / (float)NN);
            g_count = 0;   // reset for next graph replay
        }
    }
}

extern "C" void kernel_launch(void* const* d_in, const int* in_sizes, int n_in,
                              void* d_out, int out_size) {
    const float* constants = (const float*)d_in[0];   // (B,K)
    const float* scales    = (const float*)d_in[1];   // (B,K)
    const float* rotations = (const float*)d_in[2];   // (B,K,3,3)
    const float* centers   = (const float*)d_in[3];   // (B,K,3)
    const float* samples   = (const float*)d_in[4];   // (B,N,6)
    const float* grid      = (const float*)d_in[5];   // (B,GD,GD,GD)
    const float* w2g       = (const float*)d_in[6];   // (B,4,4)
    float* out = (float*)d_out;

    fused_kernel<<<TOTAL_BLK, TPB>>>(constants, scales, rotations, centers,
                                     samples, grid, w2g, out);
}